// round 13
// baseline (speedup 1.0000x reference)
#include <cuda_runtime.h>
#include <cuda_bf16.h>
#include <math.h>

// ---------------------------------------------------------------------------
// ELMo embeddings, fp32. Persistent recurrence (R9 structure) with
// slot-based grid barrier and 16-warp phase1.
// ---------------------------------------------------------------------------

namespace {
constexpr int Bn = 8;     // batch
constexpr int Tn = 96;    // time
constexpr int En = 256;   // embed dim
constexpr int Hn = 2048;  // hidden
constexpr int Pn = 256;   // projection
constexpr int Gn = 8192;  // 4*H
constexpr int NBLK = 128; // persistent grid (2 dirs x 64)
}

// scratch (device globals; allocation-free)
__device__ float g_emb[Bn * Tn * En];
__device__ float g_y0[2][Bn * Tn * Pn];
__device__ float g_y1[2][Bn * Tn * Pn];
__device__ float g_xW[2][(size_t)Tn * Bn * Gn];  // x@Wk+b, step-major
__device__ float g_h[2][Bn * Pn];
__device__ float g_a[2][Bn * Hn];
__device__ float g_mean[3][Bn];
__device__ float g_var[3][Bn];

// per-block barrier slots (monotonic generations; never reset -> replay-safe)
__device__ unsigned g_slots[NBLK];

// ---------------------------------------------------------------------------
__global__ void k_embed(const int* __restrict__ tok, const float* __restrict__ tab) {
    int i = blockIdx.x * 256 + threadIdx.x;  // B*T*E = 196608
    int bt = i >> 8;
    int e = i & 255;
    g_emb[i] = tab[(size_t)tok[bt] * En + e];
}

// ---------------------------------------------------------------------------
// xW GEMM (R9 scalar version, measured at the FFMA issue floor).
// M=768 (s,b), N=8192, K=256. BM=128 BN=128 BK=16, 256 thr, 8x8 microtile.
// ---------------------------------------------------------------------------
__global__ void __launch_bounds__(256, 2)
k_xw(const float* __restrict__ Wk, const float* __restrict__ bias, int layer) {
    const int d = blockIdx.z;
    const int widx = d * 2 + layer;
    const float* __restrict__ x = (layer == 0) ? g_emb : g_y0[d];
    const float* __restrict__ W = Wk + (size_t)widx * En * Gn;
    const float* __restrict__ bi = bias + (size_t)widx * Gn;
    float* __restrict__ out = g_xW[d];
    const int n0 = blockIdx.x * 128;
    const int m0 = blockIdx.y * 128;
    const bool rev = (d == 1);
    const int tid = threadIdx.x;
    const int tx = tid & 15;   // 8 n cols at tx*8
    const int ty = tid >> 4;   // 8 m rows at ty*8

    __shared__ float As[16][132];  // [k][m]
    __shared__ float Bs[16][128];  // [k][n]

    float acc[8][8];
#pragma unroll
    for (int i = 0; i < 8; ++i)
#pragma unroll
        for (int j = 0; j < 8; ++j) acc[i][j] = 0.f;

    // A loader: row ml, 8 k at kl
    const int ml = tid >> 1;
    const int kl = (tid & 1) * 8;
    const int m = m0 + ml;
    const int sA = m >> 3, bA = m & 7;
    const int tA = rev ? (Tn - 1 - sA) : sA;
    const float* xrow = x + (size_t)(bA * Tn + tA) * En;

    // B loader: k row kb, 8 n at nb
    const int kb = tid >> 4;
    const int nb = (tid & 15) * 8;

    for (int k0 = 0; k0 < En; k0 += 16) {
        {
            float4 v0 = *(const float4*)(xrow + k0 + kl);
            float4 v1 = *(const float4*)(xrow + k0 + kl + 4);
            As[kl + 0][ml] = v0.x;
            As[kl + 1][ml] = v0.y;
            As[kl + 2][ml] = v0.z;
            As[kl + 3][ml] = v0.w;
            As[kl + 4][ml] = v1.x;
            As[kl + 5][ml] = v1.y;
            As[kl + 6][ml] = v1.z;
            As[kl + 7][ml] = v1.w;
            const float* wr = W + (size_t)(k0 + kb) * Gn + n0 + nb;
            *(float4*)(&Bs[kb][nb]) = *(const float4*)(wr);
            *(float4*)(&Bs[kb][nb + 4]) = *(const float4*)(wr + 4);
        }
        __syncthreads();
#pragma unroll
        for (int k = 0; k < 16; ++k) {
            float4 a0 = *(const float4*)(&As[k][ty * 8]);
            float4 a1 = *(const float4*)(&As[k][ty * 8 + 4]);
            float4 b0 = *(const float4*)(&Bs[k][tx * 8]);
            float4 b1 = *(const float4*)(&Bs[k][tx * 8 + 4]);
            float av[8] = {a0.x, a0.y, a0.z, a0.w, a1.x, a1.y, a1.z, a1.w};
            float bv[8] = {b0.x, b0.y, b0.z, b0.w, b1.x, b1.y, b1.z, b1.w};
#pragma unroll
            for (int i = 0; i < 8; ++i)
#pragma unroll
                for (int j = 0; j < 8; ++j) acc[i][j] += av[i] * bv[j];
        }
        __syncthreads();
    }
    float4 bva = *(const float4*)(bi + n0 + tx * 8);
    float4 bvb = *(const float4*)(bi + n0 + tx * 8 + 4);
#pragma unroll
    for (int i = 0; i < 8; ++i) {
        int mm = m0 + ty * 8 + i;
        float* op = out + (size_t)mm * Gn + n0 + tx * 8;
        *(float4*)(op) = make_float4(acc[i][0] + bva.x, acc[i][1] + bva.y,
                                     acc[i][2] + bva.z, acc[i][3] + bva.w);
        *(float4*)(op + 4) = make_float4(acc[i][4] + bvb.x, acc[i][5] + bvb.y,
                                         acc[i][6] + bvb.z, acc[i][7] + bvb.w);
    }
}

// ---------------------------------------------------------------------------
// Persistent LSTM recurrence. 128 blocks x 512 threads, 1 block/SM.
// Block bx: dir d = bx>>6, slice q = bx&63 -> units U0=q*32, proj cols P0=q*4.
// ---------------------------------------------------------------------------
__device__ __forceinline__ float fsig(float x) {
    return __fdividef(1.f, 1.f + __expf(-x));
}
__device__ __forceinline__ float ftanh(float x) {
    return __fdividef(2.f, 1.f + __expf(-2.f * x)) - 1.f;
}

// slot barrier: each block stores its generation; warp 0 polls its dir's
// 64 slots (2 per lane). No serialized atomics.
__device__ __forceinline__ void dir_barrier(int d, unsigned gen, int tid, int bx) {
    __syncthreads();
    if (tid == 0) {
        __threadfence();
        *((volatile unsigned*)&g_slots[bx]) = gen;
    }
    if (tid < 32) {
        volatile unsigned* s = (volatile unsigned*)&g_slots[d * 64 + tid * 2];
        while ((int)(s[0] - gen) < 0 || (int)(s[1] - gen) < 0) {}
    }
    __syncthreads();
    __threadfence();
}

__global__ void __launch_bounds__(512, 1)
k_recur(const float* __restrict__ Wr, const float* __restrict__ Wp,
        const float* __restrict__ mask, int layer) {
    extern __shared__ float sm[];
    float* Wr_sm = sm;            // [256][128] (k*128+lc), lc = gate*32+u
    float* Wp_sm = sm + 32768;    // [4][2048]  (p*2048+k)
    float* hT    = sm + 40960;    // [256][8]   (p*8+b)  transposed h
    float* zpart = sm + 43008;    // [8][8][128] (kc*1024 + b*128 + lc)
    float* z_sm  = sm + 51200;    // [8][128]
    float* c_sm  = sm + 52224;    // [8][32]
    float* red   = sm + 52480;    // [8][2][4]
    // total 52544 floats = 210176 B

    const int tid = threadIdx.x;
    const int bx = blockIdx.x;
    const int d = bx >> 6;
    const int q = bx & 63;
    const int U0 = q * 32;
    const int P0 = q * 4;
    const int widx = d * 2 + layer;

    // ---- preload weights ----
    {
        const float* Wg = Wr + (size_t)widx * Pn * Gn;
        for (int i = tid; i < 256 * 128; i += 512) {
            int k = i >> 7, lc = i & 127;
            int gate = lc >> 5, u = lc & 31;
            Wr_sm[i] = __ldg(&Wg[(size_t)k * Gn + gate * Hn + U0 + u]);
        }
        const float* Wpg = Wp + (size_t)widx * Hn * Pn;
        for (int k = tid; k < Hn; k += 512) {
            float4 v = __ldg((const float4*)&Wpg[(size_t)k * Pn + P0]);
            Wp_sm[k] = v.x;
            Wp_sm[2048 + k] = v.y;
            Wp_sm[4096 + k] = v.z;
            Wp_sm[6144 + k] = v.w;
        }
    }
    if (tid < 256) c_sm[tid] = 0.f;

    const unsigned base = *((volatile unsigned*)&g_slots[bx]);
    unsigned gen = base;
    float h_own = 0.f;
    float* __restrict__ yb = (layer == 0) ? g_y0[d] : g_y1[d];
    float* __restrict__ hg = g_h[d];
    float* __restrict__ ag = g_a[d];
    const float* __restrict__ xWd = g_xW[d];
    __syncthreads();

    // role indices
    const int kc = tid >> 6;          // phase1: k-chunk (0..7, 32 k each)
    const int bh = (tid >> 5) & 1;    // phase1: batch half (4 b each)
    const int cg = tid & 31;          // phase1: 4-col group
    const int rb = tid >> 6;          // reduce: batch
    const int l2 = (tid & 63) * 2;    // reduce: 2 cols
    const int rgate = l2 >> 5, ru = l2 & 31;
    const int w = tid >> 5;           // phase2 warp
    const int lane = tid & 31;
    const int pb = w >> 1;            // phase2 batch
    const int half = w & 1;           // phase2 k half

    for (int s = 0; s < Tn; ++s) {
        const int t = d ? (Tn - 1 - s) : s;

        // prefetch xW for the reduce stage (hide DRAM latency behind phase1)
        float2 xwv = __ldcg((const float2*)&xWd[((size_t)s * Bn + rb) * Gn +
                                                rgate * Hn + U0 + ru]);

        // ---- stage h transposed: hT[p*8+b] = h[b*256+p] ----
        if (s == 0) {
            for (int i = tid; i < Bn * Pn; i += 512) hT[i] = 0.f;
        } else {
#pragma unroll
            for (int i = tid; i < Bn * Pn; i += 512) {
                int b = i >> 8, p = i & 255;
                hT[p * 8 + b] = __ldcg(&hg[i]);
            }
        }
        __syncthreads();

        // ---- phase 1: z partials = h @ Wr (8 k-chunks x 2 batch-halves,
        //      all 16 warps) ----
        {
            float acc[4][4];
#pragma unroll
            for (int b = 0; b < 4; ++b)
                acc[b][0] = acc[b][1] = acc[b][2] = acc[b][3] = 0.f;
            const float* wr0 = Wr_sm + cg * 4;
            const float* hb = hT + bh * 4;
            const int ke = kc * 32 + 32;
#pragma unroll 4
            for (int k = kc * 32; k < ke; ++k) {
                float4 wv = *(const float4*)(wr0 + k * 128);
                float4 h4 = *(const float4*)(hb + k * 8);
                float hv[4] = {h4.x, h4.y, h4.z, h4.w};
#pragma unroll
                for (int b = 0; b < 4; ++b) {
                    acc[b][0] += wv.x * hv[b];
                    acc[b][1] += wv.y * hv[b];
                    acc[b][2] += wv.z * hv[b];
                    acc[b][3] += wv.w * hv[b];
                }
            }
#pragma unroll
            for (int b = 0; b < 4; ++b)
                *(float4*)(zpart + kc * 1024 + (bh * 4 + b) * 128 + cg * 4) =
                    make_float4(acc[b][0], acc[b][1], acc[b][2], acc[b][3]);
        }
        __syncthreads();

        // ---- reduce k-chunks + add xW ----
        {
            float z0 = xwv.x, z1 = xwv.y;
#pragma unroll
            for (int kk = 0; kk < 8; ++kk) {
                float2 p = *(const float2*)(zpart + kk * 1024 + rb * 128 + l2);
                z0 += p.x;
                z1 += p.y;
            }
            *(float2*)(z_sm + rb * 128 + l2) = make_float2(z0, z1);
        }
        __syncthreads();

        // ---- gates / cell / a ----
        if (tid < 256) {
            const int b2 = tid >> 5, u = tid & 31;
            float zi = z_sm[b2 * 128 + u];
            float zf = z_sm[b2 * 128 + 32 + u];
            float zg = z_sm[b2 * 128 + 64 + u];
            float zo = z_sm[b2 * 128 + 96 + u];
            float ig = fsig(zi), fg = fsig(zf), gg = ftanh(zg), og = fsig(zo);
            float cold = c_sm[tid];
            float cn = fminf(3.f, fmaxf(-3.f, fg * cold + ig * gg));
            float mt = __ldg(&mask[b2 * Tn + t]);
            c_sm[tid] = (mt > 0.f) ? cn : cold;
            __stcg(&ag[b2 * Hn + U0 + u], og * ftanh(cn));
        }
        dir_barrier(d, ++gen, tid, bx);

        // ---- phase 2: h cols P0..P0+3 = clip(a @ Wp) ----
        {
            const float4* av4 = (const float4*)(ag + pb * Hn + half * 1024);
            float q0 = 0.f, q1 = 0.f, q2 = 0.f, q3 = 0.f;
#pragma unroll
            for (int j = 0; j < 8; ++j) {
                float4 av = __ldcg(av4 + lane + j * 32);
                const int kk = half * 1024 + (lane + j * 32) * 4;
                float4 wa = *(const float4*)&Wp_sm[kk];
                float4 wb = *(const float4*)&Wp_sm[2048 + kk];
                float4 wc = *(const float4*)&Wp_sm[4096 + kk];
                float4 wd = *(const float4*)&Wp_sm[6144 + kk];
                q0 += av.x * wa.x + av.y * wa.y + av.z * wa.z + av.w * wa.w;
                q1 += av.x * wb.x + av.y * wb.y + av.z * wb.z + av.w * wb.w;
                q2 += av.x * wc.x + av.y * wc.y + av.z * wc.z + av.w * wc.w;
                q3 += av.x * wd.x + av.y * wd.y + av.z * wd.z + av.w * wd.w;
            }
#pragma unroll
            for (int off = 16; off; off >>= 1) {
                q0 += __shfl_xor_sync(0xffffffffu, q0, off);
                q1 += __shfl_xor_sync(0xffffffffu, q1, off);
                q2 += __shfl_xor_sync(0xffffffffu, q2, off);
                q3 += __shfl_xor_sync(0xffffffffu, q3, off);
            }
            if (lane == 0)
                *(float4*)(red + (pb * 2 + half) * 4) = make_float4(q0, q1, q2, q3);
        }
        __syncthreads();
        if (tid < 32) {
            const int bb = tid >> 2, pp = tid & 3;
            float hv = red[(bb * 2) * 4 + pp] + red[(bb * 2 + 1) * 4 + pp];
            hv = fminf(3.f, fmaxf(-3.f, hv));
            float mt = __ldg(&mask[bb * Tn + t]);
            float hn = (mt > 0.f) ? hv : h_own;
            h_own = hn;
            __stcg(&hg[bb * Pn + P0 + pp], hn);
            yb[((size_t)bb * Tn + t) * Pn + P0 + pp] = hn;
        }
        dir_barrier(d, ++gen, tid, bx);
    }
}

// ---------------------------------------------------------------------------
// Epilogue (unchanged)
// ---------------------------------------------------------------------------
__device__ __forceinline__ float layer_val(int l, int b, int t, int ch) {
    if (l == 0) return g_emb[(size_t)(b * Tn + t) * En + (ch & 255)];
    const int dd = ch >> 8;
    const size_t idx = (size_t)(b * Tn + t) * Pn + (ch & 255);
    float v = g_y0[dd][idx];
    if (l == 2) v += g_y1[dd][idx];
    return v;
}

__global__ void k_stats(const float* __restrict__ mask) {
    const int b = blockIdx.x;
    const int l = blockIdx.y;
    __shared__ float red[256];
    const int tid = threadIdx.x;

    float nm = 0.f;
    for (int t = tid; t < Tn; t += 256) nm += mask[b * Tn + t];
    red[tid] = nm;
    __syncthreads();
    for (int st = 128; st > 0; st >>= 1) {
        if (tid < st) red[tid] += red[tid + st];
        __syncthreads();
    }
    const float num = red[0];
    __syncthreads();

    float smv = 0.f;
    for (int i = tid; i < Tn * 512; i += 256) {
        int t = i >> 9, ch = i & 511;
        smv += layer_val(l, b, t, ch) * mask[b * Tn + t];
    }
    red[tid] = smv;
    __syncthreads();
    for (int st = 128; st > 0; st >>= 1) {
        if (tid < st) red[tid] += red[tid + st];
        __syncthreads();
    }
    const float mean = red[0] / num;
    __syncthreads();

    float vs = 0.f;
    for (int i = tid; i < Tn * 512; i += 256) {
        int t = i >> 9, ch = i & 511;
        float m = mask[b * Tn + t];
        float dd = (layer_val(l, b, t, ch) * m - mean) * m;
        vs += dd * dd;
    }
    red[tid] = vs;
    __syncthreads();
    for (int st = 128; st > 0; st >>= 1) {
        if (tid < st) red[tid] += red[tid + st];
        __syncthreads();
    }
    if (tid == 0) {
        g_mean[l][b] = mean;
        g_var[l][b] = red[0] / num;
    }
}

__global__ void k_final(const float* __restrict__ elmo_w, const float* __restrict__ gamma,
                        float* __restrict__ out) {
    const int i = blockIdx.x * 256 + threadIdx.x;
    const int ch = i & 511;
    const int bt = i >> 9;
    const int b = bt / Tn;
    const int t = bt - b * Tn;
    float w0 = elmo_w[0], w1 = elmo_w[1], w2 = elmo_w[2];
    float mx = fmaxf(w0, fmaxf(w1, w2));
    float e0 = expf(w0 - mx), e1 = expf(w1 - mx), e2 = expf(w2 - mx);
    float inv = 1.f / (e0 + e1 + e2);
    float gm = gamma[0];
    float r = 0.f;
    r += e0 * inv * (layer_val(0, b, t, ch) - g_mean[0][b]) / sqrtf(g_var[0][b] + 1e-12f);
    r += e1 * inv * (layer_val(1, b, t, ch) - g_mean[1][b]) / sqrtf(g_var[1][b] + 1e-12f);
    r += e2 * inv * (layer_val(2, b, t, ch) - g_mean[2][b]) / sqrtf(g_var[2][b] + 1e-12f);
    out[i] = gm * r;
}

// ---------------------------------------------------------------------------
extern "C" void kernel_launch(void* const* d_in, const int* in_sizes, int n_in,
                              void* d_out, int out_size) {
    (void)in_sizes; (void)n_in; (void)out_size;
    const int*   tokens = (const int*)d_in[0];
    const float* mask   = (const float*)d_in[1];
    const float* table  = (const float*)d_in[2];
    const float* Wk     = (const float*)d_in[3];
    const float* Wr     = (const float*)d_in[4];
    const float* bias   = (const float*)d_in[5];
    const float* Wp     = (const float*)d_in[6];
    const float* elmo_w = (const float*)d_in[7];
    const float* gamma  = (const float*)d_in[8];
    float* out = (float*)d_out;

    const int recur_smem = 210176;  // 52544 floats
    cudaFuncSetAttribute(k_recur, cudaFuncAttributeMaxDynamicSharedMemorySize,
                         recur_smem);

    k_embed<<<768, 256>>>(tokens, table);
    for (int layer = 0; layer < 2; ++layer) {
        k_xw<<<dim3(Gn / 128, (Tn * Bn) / 128, 2), 256>>>(Wk, bias, layer);
        k_recur<<<NBLK, 512, recur_smem>>>(Wr, Wp, mask, layer);
    }
    k_stats<<<dim3(8, 3), 256>>>(mask);
    k_final<<<1536, 256>>>(elmo_w, gamma, out);
}

// round 14
// speedup vs baseline: 1.9976x; 1.9976x over previous
#include <cuda_runtime.h>
#include <cuda_bf16.h>
#include <math.h>

// ---------------------------------------------------------------------------
// ELMo embeddings, fp32. Persistent recurrence = R9 structure (measured best)
// with a two-level atomic grid barrier (only change vs R9).
// ---------------------------------------------------------------------------

namespace {
constexpr int Bn = 8;     // batch
constexpr int Tn = 96;    // time
constexpr int En = 256;   // embed dim
constexpr int Hn = 2048;  // hidden
constexpr int Pn = 256;   // projection
constexpr int Gn = 8192;  // 4*H
constexpr int NBLK = 128; // persistent grid (2 dirs x 64)
}

// scratch (device globals; allocation-free)
__device__ float g_emb[Bn * Tn * En];
__device__ float g_y0[2][Bn * Tn * Pn];
__device__ float g_y1[2][Bn * Tn * Pn];
__device__ float g_xW[2][(size_t)Tn * Bn * Gn];  // x@Wk+b, step-major
__device__ float g_h[2][Bn * Pn];
__device__ float g_a[2][Bn * Hn];
__device__ float g_mean[3][Bn];
__device__ float g_var[3][Bn];

// two-level barrier state (monotonic; never reset -> graph-replay safe)
__device__ unsigned g_cnt1[2][8];  // per-group arrival counters (8 blocks each)
__device__ unsigned g_cnt2[2];     // super counter (8 groups)
__device__ unsigned g_flag[2];     // release flag = barrier index

// ---------------------------------------------------------------------------
__global__ void k_embed(const int* __restrict__ tok, const float* __restrict__ tab) {
    int i = blockIdx.x * 256 + threadIdx.x;  // B*T*E = 196608
    int bt = i >> 8;
    int e = i & 255;
    g_emb[i] = tab[(size_t)tok[bt] * En + e];
}

// ---------------------------------------------------------------------------
// xW GEMM (R9 scalar version, measured at the FFMA issue floor).
// M=768 (s,b), N=8192, K=256. BM=128 BN=128 BK=16, 256 thr, 8x8 microtile.
// ---------------------------------------------------------------------------
__global__ void __launch_bounds__(256, 2)
k_xw(const float* __restrict__ Wk, const float* __restrict__ bias, int layer) {
    const int d = blockIdx.z;
    const int widx = d * 2 + layer;
    const float* __restrict__ x = (layer == 0) ? g_emb : g_y0[d];
    const float* __restrict__ W = Wk + (size_t)widx * En * Gn;
    const float* __restrict__ bi = bias + (size_t)widx * Gn;
    float* __restrict__ out = g_xW[d];
    const int n0 = blockIdx.x * 128;
    const int m0 = blockIdx.y * 128;
    const bool rev = (d == 1);
    const int tid = threadIdx.x;
    const int tx = tid & 15;   // 8 n cols at tx*8
    const int ty = tid >> 4;   // 8 m rows at ty*8

    __shared__ float As[16][132];  // [k][m]
    __shared__ float Bs[16][128];  // [k][n]

    float acc[8][8];
#pragma unroll
    for (int i = 0; i < 8; ++i)
#pragma unroll
        for (int j = 0; j < 8; ++j) acc[i][j] = 0.f;

    // A loader: row ml, 8 k at kl
    const int ml = tid >> 1;
    const int kl = (tid & 1) * 8;
    const int m = m0 + ml;
    const int sA = m >> 3, bA = m & 7;
    const int tA = rev ? (Tn - 1 - sA) : sA;
    const float* xrow = x + (size_t)(bA * Tn + tA) * En;

    // B loader: k row kb, 8 n at nb
    const int kb = tid >> 4;
    const int nb = (tid & 15) * 8;

    for (int k0 = 0; k0 < En; k0 += 16) {
        {
            float4 v0 = *(const float4*)(xrow + k0 + kl);
            float4 v1 = *(const float4*)(xrow + k0 + kl + 4);
            As[kl + 0][ml] = v0.x;
            As[kl + 1][ml] = v0.y;
            As[kl + 2][ml] = v0.z;
            As[kl + 3][ml] = v0.w;
            As[kl + 4][ml] = v1.x;
            As[kl + 5][ml] = v1.y;
            As[kl + 6][ml] = v1.z;
            As[kl + 7][ml] = v1.w;
            const float* wr = W + (size_t)(k0 + kb) * Gn + n0 + nb;
            *(float4*)(&Bs[kb][nb]) = *(const float4*)(wr);
            *(float4*)(&Bs[kb][nb + 4]) = *(const float4*)(wr + 4);
        }
        __syncthreads();
#pragma unroll
        for (int k = 0; k < 16; ++k) {
            float4 a0 = *(const float4*)(&As[k][ty * 8]);
            float4 a1 = *(const float4*)(&As[k][ty * 8 + 4]);
            float4 b0 = *(const float4*)(&Bs[k][tx * 8]);
            float4 b1 = *(const float4*)(&Bs[k][tx * 8 + 4]);
            float av[8] = {a0.x, a0.y, a0.z, a0.w, a1.x, a1.y, a1.z, a1.w};
            float bv[8] = {b0.x, b0.y, b0.z, b0.w, b1.x, b1.y, b1.z, b1.w};
#pragma unroll
            for (int i = 0; i < 8; ++i)
#pragma unroll
                for (int j = 0; j < 8; ++j) acc[i][j] += av[i] * bv[j];
        }
        __syncthreads();
    }
    float4 bva = *(const float4*)(bi + n0 + tx * 8);
    float4 bvb = *(const float4*)(bi + n0 + tx * 8 + 4);
#pragma unroll
    for (int i = 0; i < 8; ++i) {
        int mm = m0 + ty * 8 + i;
        float* op = out + (size_t)mm * Gn + n0 + tx * 8;
        *(float4*)(op) = make_float4(acc[i][0] + bva.x, acc[i][1] + bva.y,
                                     acc[i][2] + bva.z, acc[i][3] + bva.w);
        *(float4*)(op + 4) = make_float4(acc[i][4] + bvb.x, acc[i][5] + bvb.y,
                                         acc[i][6] + bvb.z, acc[i][7] + bvb.w);
    }
}

// ---------------------------------------------------------------------------
// Persistent LSTM recurrence (R9 mapping). 128 blocks x 512 threads.
// Block bx: dir d = bx>>6, slice q = bx&63 -> units U0=q*32, proj cols P0=q*4.
// ---------------------------------------------------------------------------
__device__ __forceinline__ float fsig(float x) {
    return __fdividef(1.f, 1.f + __expf(-x));
}
__device__ __forceinline__ float ftanh(float x) {
    return __fdividef(2.f, 1.f + __expf(-2.f * x)) - 1.f;
}

// two-level atomic barrier: 8 group counters (8 arrivals each) -> super
// counter (8 arrivals) -> single release flag. Only thread 0 participates;
// all counters are monotonic (exact-equality targets, wrap-safe).
__device__ __forceinline__ void dir_barrier(int d, int grp, unsigned gen, int tid) {
    __syncthreads();
    if (tid == 0) {
        __threadfence();
        unsigned v = atomicAdd(&g_cnt1[d][grp], 1u) + 1u;
        if (v == gen * 8u) {
            unsigned w = atomicAdd(&g_cnt2[d], 1u) + 1u;
            if (w == gen * 8u)
                *((volatile unsigned*)&g_flag[d]) = gen;
        }
        while ((int)(*((volatile unsigned*)&g_flag[d]) - gen) < 0) {}
    }
    __syncthreads();
    __threadfence();
}

__global__ void __launch_bounds__(512, 1)
k_recur(const float* __restrict__ Wr, const float* __restrict__ Wp,
        const float* __restrict__ mask, int layer) {
    extern __shared__ float sm[];
    float* Wr_sm = sm;            // [256][128] (k*128+lc), lc = gate*32+u
    float* Wp_sm = sm + 32768;    // [4][2048]  (p*2048+k)
    float* hT    = sm + 40960;    // [256][8]   (p*8+b)  transposed h
    float* zpart = sm + 43008;    // [8][8][128] (kc*1024 + b*128 + lc)
    float* z_sm  = sm + 51200;    // [8][128]
    float* c_sm  = sm + 52224;    // [8][32]
    float* red   = sm + 52480;    // [8][2][4]
    // total 52544 floats = 210176 B

    const int tid = threadIdx.x;
    const int bx = blockIdx.x;
    const int d = bx >> 6;
    const int q = bx & 63;
    const int grp = q >> 3;       // barrier group (8 blocks each)
    const int U0 = q * 32;
    const int P0 = q * 4;
    const int widx = d * 2 + layer;

    // ---- preload weights ----
    {
        const float* Wg = Wr + (size_t)widx * Pn * Gn;
        for (int i = tid; i < 256 * 128; i += 512) {
            int k = i >> 7, lc = i & 127;
            int gate = lc >> 5, u = lc & 31;
            Wr_sm[i] = __ldg(&Wg[(size_t)k * Gn + gate * Hn + U0 + u]);
        }
        const float* Wpg = Wp + (size_t)widx * Hn * Pn;
        for (int k = tid; k < Hn; k += 512) {
            float4 v = __ldg((const float4*)&Wpg[(size_t)k * Pn + P0]);
            Wp_sm[k] = v.x;
            Wp_sm[2048 + k] = v.y;
            Wp_sm[4096 + k] = v.z;
            Wp_sm[6144 + k] = v.w;
        }
    }
    if (tid < 256) c_sm[tid] = 0.f;

    const unsigned base = *((volatile unsigned*)&g_flag[d]);
    unsigned gen = base;
    float h_own = 0.f;
    float* __restrict__ yb = (layer == 0) ? g_y0[d] : g_y1[d];
    float* __restrict__ hg = g_h[d];
    float* __restrict__ ag = g_a[d];
    const float* __restrict__ xWd = g_xW[d];
    __syncthreads();

    // role indices
    const int kc = tid >> 5;          // phase1 (tid<256): k-chunk
    const int cg = tid & 31;          // phase1: 4-col group
    const int rb = tid >> 6;          // reduce: batch
    const int l2 = (tid & 63) * 2;    // reduce: 2 cols
    const int rgate = l2 >> 5, ru = l2 & 31;
    const int w = tid >> 5;           // phase2 warp
    const int lane = tid & 31;
    const int pb = w >> 1;            // phase2 batch
    const int half = w & 1;           // phase2 k half

    for (int s = 0; s < Tn; ++s) {
        const int t = d ? (Tn - 1 - s) : s;

        // prefetch xW for the reduce stage (hide DRAM latency behind phase1)
        float2 xwv = __ldcg((const float2*)&xWd[((size_t)s * Bn + rb) * Gn +
                                                rgate * Hn + U0 + ru]);

        // ---- stage h transposed: hT[p*8+b] = h[b*256+p] ----
        if (s == 0) {
            for (int i = tid; i < Bn * Pn; i += 512) hT[i] = 0.f;
        } else {
#pragma unroll
            for (int i = tid; i < Bn * Pn; i += 512) {
                int b = i >> 8, p = i & 255;
                hT[p * 8 + b] = __ldcg(&hg[i]);
            }
        }
        __syncthreads();

        // ---- phase 1: z partials = h @ Wr (8 k-chunks of 32) ----
        if (tid < 256) {
            float acc[8][4];
#pragma unroll
            for (int b = 0; b < 8; ++b)
                acc[b][0] = acc[b][1] = acc[b][2] = acc[b][3] = 0.f;
            const float* wr0 = Wr_sm + cg * 4;
            const int ke = kc * 32 + 32;
#pragma unroll 4
            for (int k = kc * 32; k < ke; ++k) {
                float4 wv = *(const float4*)(wr0 + k * 128);
                float h8[8];
                *(float4*)(h8) = *(const float4*)(hT + k * 8);
                *(float4*)(h8 + 4) = *(const float4*)(hT + k * 8 + 4);
#pragma unroll
                for (int b = 0; b < 8; ++b) {
                    acc[b][0] += wv.x * h8[b];
                    acc[b][1] += wv.y * h8[b];
                    acc[b][2] += wv.z * h8[b];
                    acc[b][3] += wv.w * h8[b];
                }
            }
#pragma unroll
            for (int b = 0; b < 8; ++b)
                *(float4*)(zpart + kc * 1024 + b * 128 + cg * 4) =
                    make_float4(acc[b][0], acc[b][1], acc[b][2], acc[b][3]);
        }
        __syncthreads();

        // ---- reduce k-chunks + add xW ----
        {
            float z0 = xwv.x, z1 = xwv.y;
#pragma unroll
            for (int kk = 0; kk < 8; ++kk) {
                float2 p = *(const float2*)(zpart + kk * 1024 + rb * 128 + l2);
                z0 += p.x;
                z1 += p.y;
            }
            *(float2*)(z_sm + rb * 128 + l2) = make_float2(z0, z1);
        }
        __syncthreads();

        // ---- gates / cell / a ----
        if (tid < 256) {
            const int b2 = tid >> 5, u = tid & 31;
            float zi = z_sm[b2 * 128 + u];
            float zf = z_sm[b2 * 128 + 32 + u];
            float zg = z_sm[b2 * 128 + 64 + u];
            float zo = z_sm[b2 * 128 + 96 + u];
            float ig = fsig(zi), fg = fsig(zf), gg = ftanh(zg), og = fsig(zo);
            float cold = c_sm[tid];
            float cn = fminf(3.f, fmaxf(-3.f, fg * cold + ig * gg));
            float mt = __ldg(&mask[b2 * Tn + t]);
            c_sm[tid] = (mt > 0.f) ? cn : cold;
            __stcg(&ag[b2 * Hn + U0 + u], og * ftanh(cn));
        }
        ++gen;
        dir_barrier(d, grp, gen, tid);

        // ---- phase 2: h cols P0..P0+3 = clip(a @ Wp) ----
        {
            const float4* av4 = (const float4*)(ag + pb * Hn + half * 1024);
            float q0 = 0.f, q1 = 0.f, q2 = 0.f, q3 = 0.f;
#pragma unroll
            for (int j = 0; j < 8; ++j) {
                float4 av = __ldcg(av4 + lane + j * 32);
                const int kk = half * 1024 + (lane + j * 32) * 4;
                float4 wa = *(const float4*)&Wp_sm[kk];
                float4 wb = *(const float4*)&Wp_sm[2048 + kk];
                float4 wc = *(const float4*)&Wp_sm[4096 + kk];
                float4 wd = *(const float4*)&Wp_sm[6144 + kk];
                q0 += av.x * wa.x + av.y * wa.y + av.z * wa.z + av.w * wa.w;
                q1 += av.x * wb.x + av.y * wb.y + av.z * wb.z + av.w * wb.w;
                q2 += av.x * wc.x + av.y * wc.y + av.z * wc.z + av.w * wc.w;
                q3 += av.x * wd.x + av.y * wd.y + av.z * wd.z + av.w * wd.w;
            }
#pragma unroll
            for (int off = 16; off; off >>= 1) {
                q0 += __shfl_xor_sync(0xffffffffu, q0, off);
                q1 += __shfl_xor_sync(0xffffffffu, q1, off);
                q2 += __shfl_xor_sync(0xffffffffu, q2, off);
                q3 += __shfl_xor_sync(0xffffffffu, q3, off);
            }
            if (lane == 0)
                *(float4*)(red + (pb * 2 + half) * 4) = make_float4(q0, q1, q2, q3);
        }
        __syncthreads();
        if (tid < 32) {
            const int bb = tid >> 2, pp = tid & 3;
            float hv = red[(bb * 2) * 4 + pp] + red[(bb * 2 + 1) * 4 + pp];
            hv = fminf(3.f, fmaxf(-3.f, hv));
            float mt = __ldg(&mask[bb * Tn + t]);
            float hn = (mt > 0.f) ? hv : h_own;
            h_own = hn;
            __stcg(&hg[bb * Pn + P0 + pp], hn);
            yb[((size_t)bb * Tn + t) * Pn + P0 + pp] = hn;
        }
        ++gen;
        dir_barrier(d, grp, gen, tid);
    }
}

// ---------------------------------------------------------------------------
// Epilogue (unchanged)
// ---------------------------------------------------------------------------
__device__ __forceinline__ float layer_val(int l, int b, int t, int ch) {
    if (l == 0) return g_emb[(size_t)(b * Tn + t) * En + (ch & 255)];
    const int dd = ch >> 8;
    const size_t idx = (size_t)(b * Tn + t) * Pn + (ch & 255);
    float v = g_y0[dd][idx];
    if (l == 2) v += g_y1[dd][idx];
    return v;
}

__global__ void k_stats(const float* __restrict__ mask) {
    const int b = blockIdx.x;
    const int l = blockIdx.y;
    __shared__ float red[256];
    const int tid = threadIdx.x;

    float nm = 0.f;
    for (int t = tid; t < Tn; t += 256) nm += mask[b * Tn + t];
    red[tid] = nm;
    __syncthreads();
    for (int st = 128; st > 0; st >>= 1) {
        if (tid < st) red[tid] += red[tid + st];
        __syncthreads();
    }
    const float num = red[0];
    __syncthreads();

    float smv = 0.f;
    for (int i = tid; i < Tn * 512; i += 256) {
        int t = i >> 9, ch = i & 511;
        smv += layer_val(l, b, t, ch) * mask[b * Tn + t];
    }
    red[tid] = smv;
    __syncthreads();
    for (int st = 128; st > 0; st >>= 1) {
        if (tid < st) red[tid] += red[tid + st];
        __syncthreads();
    }
    const float mean = red[0] / num;
    __syncthreads();

    float vs = 0.f;
    for (int i = tid; i < Tn * 512; i += 256) {
        int t = i >> 9, ch = i & 511;
        float m = mask[b * Tn + t];
        float dd = (layer_val(l, b, t, ch) * m - mean) * m;
        vs += dd * dd;
    }
    red[tid] = vs;
    __syncthreads();
    for (int st = 128; st > 0; st >>= 1) {
        if (tid < st) red[tid] += red[tid + st];
        __syncthreads();
    }
    if (tid == 0) {
        g_mean[l][b] = mean;
        g_var[l][b] = red[0] / num;
    }
}

__global__ void k_final(const float* __restrict__ elmo_w, const float* __restrict__ gamma,
                        float* __restrict__ out) {
    const int i = blockIdx.x * 256 + threadIdx.x;
    const int ch = i & 511;
    const int bt = i >> 9;
    const int b = bt / Tn;
    const int t = bt - b * Tn;
    float w0 = elmo_w[0], w1 = elmo_w[1], w2 = elmo_w[2];
    float mx = fmaxf(w0, fmaxf(w1, w2));
    float e0 = expf(w0 - mx), e1 = expf(w1 - mx), e2 = expf(w2 - mx);
    float inv = 1.f / (e0 + e1 + e2);
    float gm = gamma[0];
    float r = 0.f;
    r += e0 * inv * (layer_val(0, b, t, ch) - g_mean[0][b]) / sqrtf(g_var[0][b] + 1e-12f);
    r += e1 * inv * (layer_val(1, b, t, ch) - g_mean[1][b]) / sqrtf(g_var[1][b] + 1e-12f);
    r += e2 * inv * (layer_val(2, b, t, ch) - g_mean[2][b]) / sqrtf(g_var[2][b] + 1e-12f);
    out[i] = gm * r;
}

// ---------------------------------------------------------------------------
extern "C" void kernel_launch(void* const* d_in, const int* in_sizes, int n_in,
                              void* d_out, int out_size) {
    (void)in_sizes; (void)n_in; (void)out_size;
    const int*   tokens = (const int*)d_in[0];
    const float* mask   = (const float*)d_in[1];
    const float* table  = (const float*)d_in[2];
    const float* Wk     = (const float*)d_in[3];
    const float* Wr     = (const float*)d_in[4];
    const float* bias   = (const float*)d_in[5];
    const float* Wp     = (const float*)d_in[6];
    const float* elmo_w = (const float*)d_in[7];
    const float* gamma  = (const float*)d_in[8];
    float* out = (float*)d_out;

    const int recur_smem = 210176;  // 52544 floats
    cudaFuncSetAttribute(k_recur, cudaFuncAttributeMaxDynamicSharedMemorySize,
                         recur_smem);

    k_embed<<<768, 256>>>(tokens, table);
    for (int layer = 0; layer < 2; ++layer) {
        k_xw<<<dim3(Gn / 128, (Tn * Bn) / 128, 2), 256>>>(Wk, bias, layer);
        k_recur<<<NBLK, 512, recur_smem>>>(Wr, Wp, mask, layer);
    }
    k_stats<<<dim3(8, 3), 256>>>(mask);
    k_final<<<1536, 256>>>(elmo_w, gamma, out);
}

// round 15
// speedup vs baseline: 2.2018x; 1.1022x over previous
#include <cuda_runtime.h>
#include <cuda_bf16.h>
#include <mma.h>
#include <math.h>

using namespace nvcuda;

// ---------------------------------------------------------------------------
// ELMo embeddings. xW GEMM via bf16-split wmma (pre-converted operands);
// persistent fp32 LSTM recurrence (R9 structure, 16-warp phase1, R9 barrier).
// ---------------------------------------------------------------------------

namespace {
constexpr int Bn = 8;     // batch
constexpr int Tn = 96;    // time
constexpr int En = 256;   // embed dim
constexpr int Hn = 2048;  // hidden
constexpr int Pn = 256;   // projection
constexpr int Gn = 8192;  // 4*H
constexpr int NBLK = 128; // persistent grid (2 dirs x 64)
constexpr int DBLK = 64;  // blocks per direction
}

// scratch (device globals; allocation-free)
__device__ float g_emb[Bn * Tn * En];
__device__ float g_y0[2][Bn * Tn * Pn];
__device__ float g_y1[2][Bn * Tn * Pn];
__device__ float g_xW[2][(size_t)Tn * Bn * Gn];  // x@Wk (no bias), step-major
__device__ float g_h[2][Bn * Pn];
__device__ float g_a[2][Bn * Hn];
__device__ float g_mean[3][Bn];
__device__ float g_var[3][Bn];

// bf16 split operands for the xW GEMM
__device__ __nv_bfloat16 g_wkh[4 * En * Gn];  // 16.8 MB
__device__ __nv_bfloat16 g_wkl[4 * En * Gn];
__device__ __nv_bfloat16 g_xh[2][Bn * Tn * En];
__device__ __nv_bfloat16 g_xl[2][Bn * Tn * En];

// barrier state (R9: per-dir atomic counter + flag; monotonic, replay-safe)
__device__ unsigned g_cnt[2];
__device__ unsigned g_flag[2];

// ---------------------------------------------------------------------------
__global__ void k_embed(const int* __restrict__ tok, const float* __restrict__ tab) {
    int i = blockIdx.x * 256 + threadIdx.x;  // B*T*E = 196608
    int bt = i >> 8;
    int e = i & 255;
    g_emb[i] = tab[(size_t)tok[bt] * En + e];
}

// split Wk into (hi, lo) bf16 once per launch
__global__ void k_cvt_w(const float* __restrict__ Wk) {
    int i = blockIdx.x * 1024 + threadIdx.x;  // 4*256*8192 = 8388608
    float v = Wk[i];
    __nv_bfloat16 hi = __float2bfloat16(v);
    g_wkh[i] = hi;
    g_wkl[i] = __float2bfloat16(v - __bfloat162float(hi));
}

// split layer input into (hi, lo) bf16 for one dir slot
__global__ void k_cvt_x(int layer, int slot) {
    int i = blockIdx.x * 1024 + threadIdx.x;  // 768*256 = 196608
    float v = (layer == 0) ? g_emb[i] : g_y0[slot][i];
    __nv_bfloat16 hi = __float2bfloat16(v);
    g_xh[slot][i] = hi;
    g_xl[slot][i] = __float2bfloat16(v - __bfloat162float(hi));
}

// ---------------------------------------------------------------------------
// xW GEMM on bf16 tensor cores, 3-term split (hi*hi + hi*lo + lo*hi).
// M=768 (s,b), N=8192, K=256. Block 128x128, BK=32, 8 warps (2x4),
// warp tile 64x32 = 4x2 wmma m16n16k16 fragments.
// ---------------------------------------------------------------------------
__global__ void __launch_bounds__(256, 2)
k_xw_bf16(int layer) {
    const int d = blockIdx.z;
    const int widx = d * 2 + layer;
    const __nv_bfloat16* __restrict__ XH = g_xh[d];
    const __nv_bfloat16* __restrict__ XL = g_xl[d];
    const __nv_bfloat16* __restrict__ WH = g_wkh + (size_t)widx * En * Gn;
    const __nv_bfloat16* __restrict__ WL = g_wkl + (size_t)widx * En * Gn;
    float* __restrict__ out = g_xW[d];
    const int n0 = blockIdx.x * 128;
    const int m0 = blockIdx.y * 128;
    const bool rev = (d == 1);
    const int tid = threadIdx.x;

    __shared__ __nv_bfloat16 AsH[128][40];  // [m][k], pad to 40
    __shared__ __nv_bfloat16 AsL[128][40];
    __shared__ __nv_bfloat16 BsH[32][136];  // [k][n], pad to 136
    __shared__ __nv_bfloat16 BsL[32][136];

    const int wid = tid >> 5;
    const int wr = wid >> 2;       // warp row: 2 x 64 m-rows
    const int wc = wid & 3;        // warp col: 4 x 32 n-cols

    wmma::fragment<wmma::accumulator, 16, 16, 16, float> acc[4][2];
#pragma unroll
    for (int i = 0; i < 4; ++i)
#pragma unroll
        for (int j = 0; j < 2; ++j) wmma::fill_fragment(acc[i][j], 0.f);

    // A loader: row ml (0..127), 16 k at kl
    const int ml = tid >> 1;
    const int kl = (tid & 1) * 16;
    const int m = m0 + ml;
    const int sA = m >> 3, bA = m & 7;
    const int tA = rev ? (Tn - 1 - sA) : sA;
    const __nv_bfloat16* xrowH = XH + (size_t)(bA * Tn + tA) * En;
    const __nv_bfloat16* xrowL = XL + (size_t)(bA * Tn + tA) * En;

    // B loader: k row kb (0..31), 16 n at nb
    const int kb = tid >> 3;
    const int nb = (tid & 7) * 16;

    for (int k0 = 0; k0 < En; k0 += 32) {
        {
            *(uint4*)&AsH[ml][kl]     = *(const uint4*)(xrowH + k0 + kl);
            *(uint4*)&AsH[ml][kl + 8] = *(const uint4*)(xrowH + k0 + kl + 8);
            *(uint4*)&AsL[ml][kl]     = *(const uint4*)(xrowL + k0 + kl);
            *(uint4*)&AsL[ml][kl + 8] = *(const uint4*)(xrowL + k0 + kl + 8);
            const __nv_bfloat16* wH = WH + (size_t)(k0 + kb) * Gn + n0 + nb;
            const __nv_bfloat16* wL = WL + (size_t)(k0 + kb) * Gn + n0 + nb;
            *(uint4*)&BsH[kb][nb]     = *(const uint4*)(wH);
            *(uint4*)&BsH[kb][nb + 8] = *(const uint4*)(wH + 8);
            *(uint4*)&BsL[kb][nb]     = *(const uint4*)(wL);
            *(uint4*)&BsL[kb][nb + 8] = *(const uint4*)(wL + 8);
        }
        __syncthreads();
#pragma unroll
        for (int kk = 0; kk < 32; kk += 16) {
            wmma::fragment<wmma::matrix_b, 16, 16, 16, __nv_bfloat16,
                           wmma::row_major> bh[2], bl[2];
#pragma unroll
            for (int j = 0; j < 2; ++j) {
                wmma::load_matrix_sync(bh[j], &BsH[kk][wc * 32 + j * 16], 136);
                wmma::load_matrix_sync(bl[j], &BsL[kk][wc * 32 + j * 16], 136);
            }
#pragma unroll
            for (int i = 0; i < 4; ++i) {
                wmma::fragment<wmma::matrix_a, 16, 16, 16, __nv_bfloat16,
                               wmma::row_major> ah, al;
                wmma::load_matrix_sync(ah, &AsH[wr * 64 + i * 16][kk], 40);
                wmma::load_matrix_sync(al, &AsL[wr * 64 + i * 16][kk], 40);
#pragma unroll
                for (int j = 0; j < 2; ++j) {
                    wmma::mma_sync(acc[i][j], ah, bh[j], acc[i][j]);
                    wmma::mma_sync(acc[i][j], ah, bl[j], acc[i][j]);
                    wmma::mma_sync(acc[i][j], al, bh[j], acc[i][j]);
                }
            }
        }
        __syncthreads();
    }
#pragma unroll
    for (int i = 0; i < 4; ++i)
#pragma unroll
        for (int j = 0; j < 2; ++j)
            wmma::store_matrix_sync(
                out + (size_t)(m0 + wr * 64 + i * 16) * Gn + n0 + wc * 32 + j * 16,
                acc[i][j], Gn, wmma::mem_row_major);
}

// ---------------------------------------------------------------------------
// Persistent LSTM recurrence (R9 structure + 16-warp phase1 + bias in reduce).
// 128 blocks x 512 threads. Block bx: dir d = bx>>6, slice q = bx&63.
// ---------------------------------------------------------------------------
__device__ __forceinline__ float fsig(float x) {
    return __fdividef(1.f, 1.f + __expf(-x));
}
__device__ __forceinline__ float ftanh(float x) {
    return __fdividef(2.f, 1.f + __expf(-2.f * x)) - 1.f;
}

// R9 barrier: atomic arrive, thread-0 spins on one flag. (Measured best.)
__device__ __forceinline__ void dir_barrier(int d, unsigned target, int tid) {
    __syncthreads();
    if (tid == 0) {
        __threadfence();
        unsigned old = atomicAdd(&g_cnt[d], 1u);
        if (old + 1u == target)
            *((volatile unsigned*)&g_flag[d]) = target;
        while ((int)(*((volatile unsigned*)&g_flag[d]) - target) < 0) {}
    }
    __syncthreads();
    __threadfence();
}

// SMEM float offsets
namespace {
constexpr int OF_WR = 0;       // [256][128] (k*128+lc), lc = gate*32+u
constexpr int OF_WP = 32768;   // [4][2048]  (p*2048+k)
constexpr int OF_HT = 40960;   // [256][8]   (p*8+b) transposed h
constexpr int OF_ZP = 43008;   // [8][8][128] (kc*1024 + b*128 + lc)
constexpr int OF_Z  = 51200;   // [8][128]
constexpr int OF_C  = 52224;   // [8][32]
constexpr int OF_RD = 52480;   // [8][2][4]
constexpr int OF_B  = 52544;   // [128] bias slice
constexpr int SM_FLOATS = 52672;  // 210688 B
}

__global__ void __launch_bounds__(512, 1)
k_recur(const float* __restrict__ Wr, const float* __restrict__ Wp,
        const float* __restrict__ bias, const float* __restrict__ mask,
        int layer) {
    extern __shared__ float sm[];
    float* Wr_sm = sm + OF_WR;
    float* Wp_sm = sm + OF_WP;
    float* hT    = sm + OF_HT;
    float* zpart = sm + OF_ZP;
    float* z_sm  = sm + OF_Z;
    float* c_sm  = sm + OF_C;
    float* red   = sm + OF_RD;
    float* b_sm  = sm + OF_B;

    const int tid = threadIdx.x;
    const int bx = blockIdx.x;
    const int d = bx >> 6;
    const int q = bx & 63;
    const int U0 = q * 32;
    const int P0 = q * 4;
    const int widx = d * 2 + layer;

    // ---- preload weights + bias slice ----
    {
        const float* Wg = Wr + (size_t)widx * Pn * Gn;
        for (int i = tid; i < 256 * 128; i += 512) {
            int k = i >> 7, lc = i & 127;
            int gate = lc >> 5, u = lc & 31;
            Wr_sm[i] = __ldg(&Wg[(size_t)k * Gn + gate * Hn + U0 + u]);
        }
        const float* Wpg = Wp + (size_t)widx * Hn * Pn;
        for (int k = tid; k < Hn; k += 512) {
            float4 v = __ldg((const float4*)&Wpg[(size_t)k * Pn + P0]);
            Wp_sm[k] = v.x;
            Wp_sm[2048 + k] = v.y;
            Wp_sm[4096 + k] = v.z;
            Wp_sm[6144 + k] = v.w;
        }
        if (tid < 128) {
            int gate = tid >> 5, u = tid & 31;
            b_sm[tid] = __ldg(&bias[(size_t)widx * Gn + gate * Hn + U0 + u]);
        }
    }
    if (tid < 256) c_sm[tid] = 0.f;

    const unsigned base = *((volatile unsigned*)&g_flag[d]);
    unsigned target = base;
    float h_own = 0.f;
    float* __restrict__ yb = (layer == 0) ? g_y0[d] : g_y1[d];
    float* __restrict__ hg = g_h[d];
    float* __restrict__ ag = g_a[d];
    const float* __restrict__ xWd = g_xW[d];
    __syncthreads();

    // role indices
    const int kc = tid >> 6;          // phase1: k-chunk (0..7, 32 k each)
    const int bh = (tid >> 5) & 1;    // phase1: batch half (4 b each)
    const int cg = tid & 31;          // phase1: 4-col group
    const int rb = tid >> 6;          // reduce: batch
    const int l2 = (tid & 63) * 2;    // reduce: 2 cols
    const int rgate = l2 >> 5, ru = l2 & 31;
    const int w = tid >> 5;           // phase2 warp
    const int lane = tid & 31;
    const int pb = w >> 1;            // phase2 batch
    const int half = w & 1;           // phase2 k half

    for (int s = 0; s < Tn; ++s) {
        const int t = d ? (Tn - 1 - s) : s;

        // prefetch xW for the reduce stage (hide DRAM latency behind phase1)
        float2 xwv = __ldcg((const float2*)&xWd[((size_t)s * Bn + rb) * Gn +
                                                rgate * Hn + U0 + ru]);

        // ---- stage h transposed: hT[p*8+b] = h[b*256+p] ----
        if (s == 0) {
            for (int i = tid; i < Bn * Pn; i += 512) hT[i] = 0.f;
        } else {
#pragma unroll
            for (int i = tid; i < Bn * Pn; i += 512) {
                int b = i >> 8, p = i & 255;
                hT[p * 8 + b] = __ldcg(&hg[i]);
            }
        }
        __syncthreads();

        // ---- phase 1: z partials = h @ Wr (8 k-chunks x 2 b-halves, 16 warps) ----
        {
            float acc[4][4];
#pragma unroll
            for (int b = 0; b < 4; ++b)
                acc[b][0] = acc[b][1] = acc[b][2] = acc[b][3] = 0.f;
            const float* wr0 = Wr_sm + cg * 4;
            const float* hb = hT + bh * 4;
            const int ke = kc * 32 + 32;
#pragma unroll 4
            for (int k = kc * 32; k < ke; ++k) {
                float4 wv = *(const float4*)(wr0 + k * 128);
                float4 h4 = *(const float4*)(hb + k * 8);
                float hv[4] = {h4.x, h4.y, h4.z, h4.w};
#pragma unroll
                for (int b = 0; b < 4; ++b) {
                    acc[b][0] += wv.x * hv[b];
                    acc[b][1] += wv.y * hv[b];
                    acc[b][2] += wv.z * hv[b];
                    acc[b][3] += wv.w * hv[b];
                }
            }
#pragma unroll
            for (int b = 0; b < 4; ++b)
                *(float4*)(zpart + kc * 1024 + (bh * 4 + b) * 128 + cg * 4) =
                    make_float4(acc[b][0], acc[b][1], acc[b][2], acc[b][3]);
        }
        __syncthreads();

        // ---- reduce k-chunks + add xW + bias ----
        {
            float z0 = xwv.x + b_sm[l2];
            float z1 = xwv.y + b_sm[l2 + 1];
#pragma unroll
            for (int kk = 0; kk < 8; ++kk) {
                float2 p = *(const float2*)(zpart + kk * 1024 + rb * 128 + l2);
                z0 += p.x;
                z1 += p.y;
            }
            *(float2*)(z_sm + rb * 128 + l2) = make_float2(z0, z1);
        }
        __syncthreads();

        // ---- gates / cell / a ----
        if (tid < 256) {
            const int b2 = tid >> 5, u = tid & 31;
            float zi = z_sm[b2 * 128 + u];
            float zf = z_sm[b2 * 128 + 32 + u];
            float zg = z_sm[b2 * 128 + 64 + u];
            float zo = z_sm[b2 * 128 + 96 + u];
            float ig = fsig(zi), fg = fsig(zf), gg = ftanh(zg), og = fsig(zo);
            float cold = c_sm[tid];
            float cn = fminf(3.f, fmaxf(-3.f, fg * cold + ig * gg));
            float mt = __ldg(&mask[b2 * Tn + t]);
            c_sm[tid] = (mt > 0.f) ? cn : cold;
            __stcg(&ag[b2 * Hn + U0 + u], og * ftanh(cn));
        }
        target += DBLK;
        dir_barrier(d, target, tid);

        // ---- phase 2: h cols P0..P0+3 = clip(a @ Wp) ----
        {
            const float4* av4 = (const float4*)(ag + pb * Hn + half * 1024);
            float q0 = 0.f, q1 = 0.f, q2 = 0.f, q3 = 0.f;
#pragma unroll
            for (int j = 0; j < 8; ++j) {
                float4 av = __ldcg(av4 + lane + j * 32);
                const int kk = half * 1024 + (lane + j * 32) * 4;
                float4 wa = *(const float4*)&Wp_sm[kk];
                float4 wb = *(const float4*)&Wp_sm[2048 + kk];
                float4 wc = *(const float4*)&Wp_sm[4096 + kk];
                float4 wd = *(const float4*)&Wp_sm[6144 + kk];
                q0 += av.x * wa.x + av.y * wa.y + av.z * wa.z + av.w * wa.w;
                q1 += av.x * wb.x + av.y * wb.y + av.z * wb.z + av.w * wb.w;
                q2 += av.x * wc.x + av.y * wc.y + av.z * wc.z + av.w * wc.w;
                q3 += av.x * wd.x + av.y * wd.y + av.z * wd.z + av.w * wd.w;
            }
#pragma unroll
            for (int off = 16; off; off >>= 1) {
                q0 += __shfl_xor_sync(0xffffffffu, q0, off);
                q1 += __shfl_xor_sync(0xffffffffu, q1, off);
                q2 += __shfl_xor_sync(0xffffffffu, q2, off);
                q3 += __shfl_xor_sync(0xffffffffu, q3, off);
            }
            if (lane == 0)
                *(float4*)(red + (pb * 2 + half) * 4) = make_float4(q0, q1, q2, q3);
        }
        __syncthreads();
        if (tid < 32) {
            const int bb = tid >> 2, pp = tid & 3;
            float hv = red[(bb * 2) * 4 + pp] + red[(bb * 2 + 1) * 4 + pp];
            hv = fminf(3.f, fmaxf(-3.f, hv));
            float mt = __ldg(&mask[bb * Tn + t]);
            float hn = (mt > 0.f) ? hv : h_own;
            h_own = hn;
            __stcg(&hg[bb * Pn + P0 + pp], hn);
            yb[((size_t)bb * Tn + t) * Pn + P0 + pp] = hn;
        }
        target += DBLK;
        dir_barrier(d, target, tid);
    }
}

// ---------------------------------------------------------------------------
// Epilogue (unchanged)
// ---------------------------------------------------------------------------
__device__ __forceinline__ float layer_val(int l, int b, int t, int ch) {
    if (l == 0) return g_emb[(size_t)(b * Tn + t) * En + (ch & 255)];
    const int dd = ch >> 8;
    const size_t idx = (size_t)(b * Tn + t) * Pn + (ch & 255);
    float v = g_y0[dd][idx];
    if (l == 2) v += g_y1[dd][idx];
    return v;
}

__global__ void k_stats(const float* __restrict__ mask) {
    const int b = blockIdx.x;
    const int l = blockIdx.y;
    __shared__ float red[256];
    const int tid = threadIdx.x;

    float nm = 0.f;
    for (int t = tid; t < Tn; t += 256) nm += mask[b * Tn + t];
    red[tid] = nm;
    __syncthreads();
    for (int st = 128; st > 0; st >>= 1) {
        if (tid < st) red[tid] += red[tid + st];
        __syncthreads();
    }
    const float num = red[0];
    __syncthreads();

    float smv = 0.f;
    for (int i = tid; i < Tn * 512; i += 256) {
        int t = i >> 9, ch = i & 511;
        smv += layer_val(l, b, t, ch) * mask[b * Tn + t];
    }
    red[tid] = smv;
    __syncthreads();
    for (int st = 128; st > 0; st >>= 1) {
        if (tid < st) red[tid] += red[tid + st];
        __syncthreads();
    }
    const float mean = red[0] / num;
    __syncthreads();

    float vs = 0.f;
    for (int i = tid; i < Tn * 512; i += 256) {
        int t = i >> 9, ch = i & 511;
        float m = mask[b * Tn + t];
        float dd = (layer_val(l, b, t, ch) * m - mean) * m;
        vs += dd * dd;
    }
    red[tid] = vs;
    __syncthreads();
    for (int st = 128; st > 0; st >>= 1) {
        if (tid < st) red[tid] += red[tid + st];
        __syncthreads();
    }
    if (tid == 0) {
        g_mean[l][b] = mean;
        g_var[l][b] = red[0] / num;
    }
}

__global__ void k_final(const float* __restrict__ elmo_w, const float* __restrict__ gamma,
                        float* __restrict__ out) {
    const int i = blockIdx.x * 256 + threadIdx.x;
    const int ch = i & 511;
    const int bt = i >> 9;
    const int b = bt / Tn;
    const int t = bt - b * Tn;
    float w0 = elmo_w[0], w1 = elmo_w[1], w2 = elmo_w[2];
    float mx = fmaxf(w0, fmaxf(w1, w2));
    float e0 = expf(w0 - mx), e1 = expf(w1 - mx), e2 = expf(w2 - mx);
    float inv = 1.f / (e0 + e1 + e2);
    float gm = gamma[0];
    float r = 0.f;
    r += e0 * inv * (layer_val(0, b, t, ch) - g_mean[0][b]) / sqrtf(g_var[0][b] + 1e-12f);
    r += e1 * inv * (layer_val(1, b, t, ch) - g_mean[1][b]) / sqrtf(g_var[1][b] + 1e-12f);
    r += e2 * inv * (layer_val(2, b, t, ch) - g_mean[2][b]) / sqrtf(g_var[2][b] + 1e-12f);
    out[i] = gm * r;
}

// ---------------------------------------------------------------------------
extern "C" void kernel_launch(void* const* d_in, const int* in_sizes, int n_in,
                              void* d_out, int out_size) {
    (void)in_sizes; (void)n_in; (void)out_size;
    const int*   tokens = (const int*)d_in[0];
    const float* mask   = (const float*)d_in[1];
    const float* table  = (const float*)d_in[2];
    const float* Wk     = (const float*)d_in[3];
    const float* Wr     = (const float*)d_in[4];
    const float* bias   = (const float*)d_in[5];
    const float* Wp     = (const float*)d_in[6];
    const float* elmo_w = (const float*)d_in[7];
    const float* gamma  = (const float*)d_in[8];
    float* out = (float*)d_out;

    const int recur_smem = SM_FLOATS * 4;  // 210688 B
    cudaFuncSetAttribute(k_recur, cudaFuncAttributeMaxDynamicSharedMemorySize,
                         recur_smem);

    k_embed<<<768, 256>>>(tokens, table);
    k_cvt_w<<<8192, 1024>>>(Wk);
    for (int layer = 0; layer < 2; ++layer) {
        k_cvt_x<<<192, 1024>>>(layer, 0);
        k_cvt_x<<<192, 1024>>>(layer, 1);
        k_xw_bf16<<<dim3(Gn / 128, (Tn * Bn) / 128, 2), 256>>>(layer);
        k_recur<<<NBLK, 512, recur_smem>>>(Wr, Wp, bias, mask, layer);
    }
    k_stats<<<dim3(8, 3), 256>>>(mask);
    k_final<<<1536, 256>>>(elmo_w, gamma, out);
}